// round 1
// baseline (speedup 1.0000x reference)
#include <cuda_runtime.h>

#define NN 50000
#define EE 800000
#define TT 24
#define ETOT (EE + NN)

// ---------------- scratch (static device globals; no allocations) ----------------
__device__ float g_h2last[NN * 64];        // LSTM layer-2 final hidden
__device__ float g_xl[NN * 128];           // GAT node features (H*C)
__device__ float g_asrc[NN * 4];
__device__ float g_adst[NN * 4];
__device__ float g_max[NN * 4];            // segment max (float via int bits)
__device__ float g_denom[NN * 4];          // softmax denominators
__device__ float g_accum[NN * 128];        // aggregated messages
__device__ float g_ex[(long long)ETOT * 4];// per-edge exp / alpha
__device__ float g_meansum;                // sum of edge_attr
__device__ float g_K[4];                   // a_edge = ea * K[h]
__device__ int   g_idx64;                  // edge_index dtype flag

// ---------------- helpers ----------------
__device__ __forceinline__ float sigf(float x) {
    return __fdividef(1.f, 1.f + __expf(-x));
}
__device__ __forceinline__ float tanhfastf(float x) {
    return 1.f - __fdividef(2.f, __expf(2.f * x) + 1.f);
}
__device__ __forceinline__ long long eidx(const void* ei, long long pos) {
    if (g_idx64) return ((const long long*)ei)[pos];
    return (long long)((const int*)ei)[pos];
}
__device__ __forceinline__ void atomicMaxF(float* addr, float val) {
    if (val >= 0.f) atomicMax((int*)addr, __float_as_int(val));
    else            atomicMin((unsigned int*)addr, __float_as_uint(val));
}

// ---------------- K0: init scratch + per-head edge constant ----------------
__global__ void init_kernel(const float* __restrict__ lin_edge_w,
                            const float* __restrict__ att_edge) {
    long long stride = (long long)gridDim.x * blockDim.x;
    long long i0 = (long long)blockIdx.x * blockDim.x + threadIdx.x;
    for (long long i = i0; i < (long long)NN * 128; i += stride) g_accum[i] = 0.f;
    for (long long i = i0; i < (long long)NN * 4; i += stride) {
        g_denom[i] = 0.f;
        ((int*)g_max)[i] = 0xFF800000;  // -inf
    }
    if (i0 == 0) g_meansum = 0.f;
    if (i0 < 4) {
        float s = 0.f;
        for (int c = 0; c < 32; c++) s += lin_edge_w[i0 * 32 + c] * att_edge[i0 * 32 + c];
        g_K[i0] = s;
    }
}

// ---------------- detect edge_index dtype (int64 vs int32) ----------------
__global__ void detect_kernel(const long long* __restrict__ ei) {
    if (blockIdx.x == 0 && threadIdx.x == 0) {
        int ok = 1;
        for (int i = 0; i < 512; i++) {
            long long v = ei[i];
            if (v < 0 || v >= NN) { ok = 0; break; }
        }
        g_idx64 = ok;
    }
}

// ---------------- K1: mean of edge_attr ----------------
__global__ void mean_kernel(const float* __restrict__ ea) {
    __shared__ float red[256];
    float s = 0.f;
    for (long long i = (long long)blockIdx.x * blockDim.x + threadIdx.x; i < EE;
         i += (long long)gridDim.x * blockDim.x)
        s += ea[i];
    red[threadIdx.x] = s;
    __syncthreads();
    for (int o = 128; o; o >>= 1) {
        if (threadIdx.x < o) red[threadIdx.x] += red[threadIdx.x + o];
        __syncthreads();
    }
    if (threadIdx.x == 0) atomicAdd(&g_meansum, red[0]);
}

// ---------------- K2: fused 2-layer LSTM, 32 nodes/block ----------------
__global__ void __launch_bounds__(256, 1) lstm_kernel(
    const float* __restrict__ x,
    const float* __restrict__ w_ih0, const float* __restrict__ w_hh0,
    const float* __restrict__ b_ih0, const float* __restrict__ b_hh0,
    const float* __restrict__ w_ih1, const float* __restrict__ w_hh1,
    const float* __restrict__ b_ih1, const float* __restrict__ b_hh1) {
    extern __shared__ float sm[];
    float* wT0   = sm;                 // [64][256] w_hh0 transposed
    float* wTi1  = wT0 + 64 * 256;     // [64][256] w_ih1 transposed
    float* wTh1  = wTi1 + 64 * 256;    // [64][256] w_hh1 transposed
    float* bias0 = wTh1 + 64 * 256;    // 256
    float* bias1 = bias0 + 256;        // 256
    float* wi0v  = bias1 + 256;        // 256 (w_ih0 column)
    float* h0s   = wi0v + 256;         // [32][64]
    float* h1s   = h0s + 32 * 64;      // [32][64]
    float* xcur  = h1s + 32 * 64;      // [32]

    const int tid = threadIdx.x;
    for (int i = tid; i < 64 * 256; i += 256) {
        int k = i >> 8, g = i & 255;
        wT0[i]  = w_hh0[g * 64 + k];
        wTi1[i] = w_ih1[g * 64 + k];
        wTh1[i] = w_hh1[g * 64 + k];
    }
    bias0[tid] = b_ih0[tid] + b_hh0[tid];
    bias1[tid] = b_ih1[tid] + b_hh1[tid];
    wi0v[tid]  = w_ih0[tid];
    for (int i = tid; i < 32 * 64; i += 256) { h0s[i] = 0.f; h1s[i] = 0.f; }
    __syncthreads();

    const int j  = tid & 63;   // hidden unit index
    const int ng = tid >> 6;   // node subgroup (8 nodes)
    const float* hb0 = h0s + ng * 8 * 64;
    const float* hb1 = h1s + ng * 8 * 64;

    float c0[8], c1[8];
#pragma unroll
    for (int n = 0; n < 8; n++) { c0[n] = 0.f; c1[n] = 0.f; }

    const float bi0 = bias0[j], bf0 = bias0[64 + j], bg0 = bias0[128 + j], bo0 = bias0[192 + j];
    const float bi1 = bias1[j], bf1 = bias1[64 + j], bg1 = bias1[128 + j], bo1 = bias1[192 + j];
    const float wxi = wi0v[j], wxf = wi0v[64 + j], wxg = wi0v[128 + j], wxo = wi0v[192 + j];

    for (int t = 0; t < TT; t++) {
        if (tid < 32) {
            int node = blockIdx.x * 32 + tid;
            xcur[tid] = (node < NN) ? x[node * 32 + 8 + t] : 0.f;
        }
        __syncthreads();

        // ---- layer 0: gates = h0 @ w_hh0^T (+ x*w_ih0 + biases) ----
        float ai[8], af[8], ag[8], ao[8];
#pragma unroll
        for (int n = 0; n < 8; n++) { ai[n] = af[n] = ag[n] = ao[n] = 0.f; }
#pragma unroll 4
        for (int k = 0; k < 64; k++) {
            const float* wr = wT0 + k * 256;
            float wi = wr[j], wf = wr[64 + j], wg = wr[128 + j], wo = wr[192 + j];
#pragma unroll
            for (int n = 0; n < 8; n++) {
                float h = hb0[n * 64 + k];
                ai[n] += wi * h; af[n] += wf * h; ag[n] += wg * h; ao[n] += wo * h;
            }
        }
        float hnew[8];
#pragma unroll
        for (int n = 0; n < 8; n++) {
            float xv = xcur[ng * 8 + n];
            float gi = ai[n] + xv * wxi + bi0;
            float gf = af[n] + xv * wxf + bf0;
            float gg = ag[n] + xv * wxg + bg0;
            float go = ao[n] + xv * wxo + bo0;
            c0[n] = sigf(gf) * c0[n] + sigf(gi) * tanhfastf(gg);
            hnew[n] = sigf(go) * tanhfastf(c0[n]);
        }
        __syncthreads();
#pragma unroll
        for (int n = 0; n < 8; n++) h0s[(ng * 8 + n) * 64 + j] = hnew[n];
        __syncthreads();

        // ---- layer 1: gates = h0_new @ w_ih1^T + h1 @ w_hh1^T + biases ----
#pragma unroll
        for (int n = 0; n < 8; n++) { ai[n] = af[n] = ag[n] = ao[n] = 0.f; }
#pragma unroll 4
        for (int k = 0; k < 64; k++) {
            const float* wr = wTi1 + k * 256;
            float wi = wr[j], wf = wr[64 + j], wg = wr[128 + j], wo = wr[192 + j];
#pragma unroll
            for (int n = 0; n < 8; n++) {
                float h = hb0[n * 64 + k];
                ai[n] += wi * h; af[n] += wf * h; ag[n] += wg * h; ao[n] += wo * h;
            }
        }
#pragma unroll 4
        for (int k = 0; k < 64; k++) {
            const float* wr = wTh1 + k * 256;
            float wi = wr[j], wf = wr[64 + j], wg = wr[128 + j], wo = wr[192 + j];
#pragma unroll
            for (int n = 0; n < 8; n++) {
                float h = hb1[n * 64 + k];
                ai[n] += wi * h; af[n] += wf * h; ag[n] += wg * h; ao[n] += wo * h;
            }
        }
#pragma unroll
        for (int n = 0; n < 8; n++) {
            float gi = ai[n] + bi1;
            float gf = af[n] + bf1;
            float gg = ag[n] + bg1;
            float go = ao[n] + bo1;
            c1[n] = sigf(gf) * c1[n] + sigf(gi) * tanhfastf(gg);
            hnew[n] = sigf(go) * tanhfastf(c1[n]);
        }
        __syncthreads();
#pragma unroll
        for (int n = 0; n < 8; n++) h1s[(ng * 8 + n) * 64 + j] = hnew[n];
        __syncthreads();
    }

    for (int i = tid; i < 32 * 64; i += 256) {
        int node = blockIdx.x * 32 + (i >> 6);
        if (node < NN) g_h2last[node * 64 + (i & 63)] = h1s[i];
    }
}

// ---------------- K3: xl = combined @ lin_w^T ; a_src, a_dst ----------------
__global__ void node_feat_kernel(const float* __restrict__ x,
                                 const float* __restrict__ lin_w,
                                 const float* __restrict__ att_src,
                                 const float* __restrict__ att_dst) {
    __shared__ float sW[72 * 128];   // [d][g]
    __shared__ float scomb[8][72];
    __shared__ float ssrc[128], sdst[128];
    int tid = threadIdx.x;
    for (int i = tid; i < 72 * 128; i += 256) {
        int d = i >> 7, g = i & 127;
        sW[i] = lin_w[g * 72 + d];
    }
    if (tid < 128) { ssrc[tid] = att_src[tid]; sdst[tid] = att_dst[tid]; }
    int nl = tid >> 5, lane = tid & 31;
    int node = blockIdx.x * 8 + nl;
    for (int d = lane; d < 72; d += 32)
        scomb[nl][d] = (node < NN) ? (d < 64 ? g_h2last[node * 64 + d]
                                             : x[node * 32 + (d - 64)])
                                   : 0.f;
    __syncthreads();
    float o0 = 0.f, o1 = 0.f, o2 = 0.f, o3 = 0.f;
    for (int d = 0; d < 72; d++) {
        float cv = scomb[nl][d];
        const float4 w4 = *(const float4*)&sW[d * 128 + lane * 4];
        o0 += cv * w4.x; o1 += cv * w4.y; o2 += cv * w4.z; o3 += cv * w4.w;
    }
    float ps = o0 * ssrc[lane * 4] + o1 * ssrc[lane * 4 + 1] +
               o2 * ssrc[lane * 4 + 2] + o3 * ssrc[lane * 4 + 3];
    float pd = o0 * sdst[lane * 4] + o1 * sdst[lane * 4 + 1] +
               o2 * sdst[lane * 4 + 2] + o3 * sdst[lane * 4 + 3];
    for (int off = 4; off; off >>= 1) {
        ps += __shfl_down_sync(0xffffffffu, ps, off, 8);
        pd += __shfl_down_sync(0xffffffffu, pd, off, 8);
    }
    if (node < NN) {
        *(float4*)&g_xl[node * 128 + lane * 4] = make_float4(o0, o1, o2, o3);
        if ((lane & 7) == 0) {
            int h = lane >> 3;
            g_asrc[node * 4 + h] = ps;
            g_adst[node * 4 + h] = pd;
        }
    }
}

// ---------------- per-edge logit ----------------
__device__ __forceinline__ void edge_logits(const void* ei, const float* ea,
                                            long long e, long long& s, long long& d,
                                            float lg[4]) {
    float a;
    if (e < EE) {
        s = eidx(ei, e);
        d = eidx(ei, (long long)EE + e);
        a = ea[e];
    } else {
        s = d = e - EE;
        a = g_meansum * (1.f / EE);
    }
    const float4 as = *(const float4*)&g_asrc[s * 4];
    const float4 ad = *(const float4*)&g_adst[d * 4];
    const float4 Kv = *(const float4*)g_K;
    lg[0] = as.x + ad.x + a * Kv.x;
    lg[1] = as.y + ad.y + a * Kv.y;
    lg[2] = as.z + ad.z + a * Kv.z;
    lg[3] = as.w + ad.w + a * Kv.w;
#pragma unroll
    for (int h = 0; h < 4; h++) lg[h] = lg[h] > 0.f ? lg[h] : 0.2f * lg[h];
}

// ---------------- K4: segment max ----------------
__global__ void logit_max_kernel(const void* __restrict__ ei, const float* __restrict__ ea) {
    long long e = (long long)blockIdx.x * blockDim.x + threadIdx.x;
    if (e >= ETOT) return;
    long long s, d;
    float lg[4];
    edge_logits(ei, ea, e, s, d, lg);
#pragma unroll
    for (int h = 0; h < 4; h++) atomicMaxF(&g_max[d * 4 + h], lg[h]);
}

// ---------------- K5: ex + denom ----------------
__global__ void softmax_kernel(const void* __restrict__ ei, const float* __restrict__ ea) {
    long long e = (long long)blockIdx.x * blockDim.x + threadIdx.x;
    if (e >= ETOT) return;
    long long s, d;
    float lg[4];
    edge_logits(ei, ea, e, s, d, lg);
    const float4 mv = *(const float4*)&g_max[d * 4];
    float e0 = __expf(lg[0] - mv.x);
    float e1 = __expf(lg[1] - mv.y);
    float e2 = __expf(lg[2] - mv.z);
    float e3 = __expf(lg[3] - mv.w);
    *(float4*)&g_ex[e * 4] = make_float4(e0, e1, e2, e3);
    atomicAdd(&g_denom[d * 4 + 0], e0);
    atomicAdd(&g_denom[d * 4 + 1], e1);
    atomicAdd(&g_denom[d * 4 + 2], e2);
    atomicAdd(&g_denom[d * 4 + 3], e3);
}

// ---------------- K5b: alpha = ex / (denom + eps) in place ----------------
__global__ void alpha_kernel(const void* __restrict__ ei) {
    long long e = (long long)blockIdx.x * blockDim.x + threadIdx.x;
    if (e >= ETOT) return;
    long long d = (e < EE) ? eidx(ei, (long long)EE + e) : (e - EE);
    float4 exv = *(const float4*)&g_ex[e * 4];
    const float4 dn = *(const float4*)&g_denom[d * 4];
    exv.x = exv.x / (dn.x + 1e-16f);
    exv.y = exv.y / (dn.y + 1e-16f);
    exv.z = exv.z / (dn.z + 1e-16f);
    exv.w = exv.w / (dn.w + 1e-16f);
    *(float4*)&g_ex[e * 4] = exv;
}

// ---------------- K6: message scatter (32 lanes per edge) ----------------
__global__ void message_kernel(const void* __restrict__ ei) {
    long long idx = (long long)blockIdx.x * blockDim.x + threadIdx.x;
    long long e = idx >> 5;
    int lane = (int)(idx & 31);
    if (e >= ETOT) return;
    long long s, d;
    if (e < EE) {
        s = eidx(ei, e);
        d = eidx(ei, (long long)EE + e);
    } else {
        s = d = e - EE;
    }
    const float4 al = *(const float4*)&g_ex[e * 4];
    atomicAdd(&g_accum[d * 128 + 0 * 32 + lane], g_xl[s * 128 + 0 * 32 + lane] * al.x);
    atomicAdd(&g_accum[d * 128 + 1 * 32 + lane], g_xl[s * 128 + 1 * 32 + lane] * al.y);
    atomicAdd(&g_accum[d * 128 + 2 * 32 + lane], g_xl[s * 128 + 2 * 32 + lane] * al.z);
    atomicAdd(&g_accum[d * 128 + 3 * 32 + lane], g_xl[s * 128 + 3 * 32 + lane] * al.w);
}

// ---------------- K7: bias + elu + fc + relu ----------------
__global__ void out_kernel(const float* __restrict__ gat_bias,
                           const float* __restrict__ fc_w,
                           const float* __restrict__ fc_b,
                           float* __restrict__ out) {
    long long idx = (long long)blockIdx.x * blockDim.x + threadIdx.x;
    int node = (int)(idx >> 5), lane = (int)(idx & 31);
    if (node >= NN) return;
    float a0 = 0.f, a1 = 0.f, a2 = 0.f, a3 = 0.f;
    const float4 av = *(const float4*)&g_accum[node * 128 + lane * 4];
    const float4 bv = *(const float4*)&gat_bias[lane * 4];
    float v[4] = {av.x + bv.x, av.y + bv.y, av.z + bv.z, av.w + bv.w};
#pragma unroll
    for (int r = 0; r < 4; r++) {
        float vv = v[r] > 0.f ? v[r] : expm1f(v[r]);
        int hc = lane * 4 + r;
        a0 += vv * fc_w[0 * 128 + hc];
        a1 += vv * fc_w[1 * 128 + hc];
        a2 += vv * fc_w[2 * 128 + hc];
        a3 += vv * fc_w[3 * 128 + hc];
    }
    for (int off = 16; off; off >>= 1) {
        a0 += __shfl_down_sync(0xffffffffu, a0, off);
        a1 += __shfl_down_sync(0xffffffffu, a1, off);
        a2 += __shfl_down_sync(0xffffffffu, a2, off);
        a3 += __shfl_down_sync(0xffffffffu, a3, off);
    }
    if (lane == 0) {
        out[node * 4 + 0] = fmaxf(a0 + fc_b[0], 0.f);
        out[node * 4 + 1] = fmaxf(a1 + fc_b[1], 0.f);
        out[node * 4 + 2] = fmaxf(a2 + fc_b[2], 0.f);
        out[node * 4 + 3] = fmaxf(a3 + fc_b[3], 0.f);
    }
}

// ---------------- launch ----------------
extern "C" void kernel_launch(void* const* d_in, const int* in_sizes, int n_in,
                              void* d_out, int out_size) {
    const float* x        = (const float*)d_in[0];
    const void*  ei       = d_in[1];
    const float* ea       = (const float*)d_in[2];
    const float* w_ih0    = (const float*)d_in[3];
    const float* w_hh0    = (const float*)d_in[4];
    const float* b_ih0    = (const float*)d_in[5];
    const float* b_hh0    = (const float*)d_in[6];
    const float* w_ih1    = (const float*)d_in[7];
    const float* w_hh1    = (const float*)d_in[8];
    const float* b_ih1    = (const float*)d_in[9];
    const float* b_hh1    = (const float*)d_in[10];
    const float* lin_w    = (const float*)d_in[11];
    const float* lin_ew   = (const float*)d_in[12];
    const float* att_src  = (const float*)d_in[13];
    const float* att_dst  = (const float*)d_in[14];
    const float* att_edge = (const float*)d_in[15];
    const float* gat_bias = (const float*)d_in[16];
    const float* fc_w     = (const float*)d_in[17];
    const float* fc_b     = (const float*)d_in[18];
    float* out = (float*)d_out;

    const int lstm_smem = (3 * 64 * 256 + 3 * 256 + 2 * 32 * 64 + 32) * (int)sizeof(float);
    cudaFuncSetAttribute(lstm_kernel, cudaFuncAttributeMaxDynamicSharedMemorySize, lstm_smem);

    init_kernel<<<2048, 256>>>(lin_ew, att_edge);
    detect_kernel<<<1, 32>>>((const long long*)ei);
    mean_kernel<<<256, 256>>>(ea);
    lstm_kernel<<<(NN + 31) / 32, 256, lstm_smem>>>(x, w_ih0, w_hh0, b_ih0, b_hh0,
                                                    w_ih1, w_hh1, b_ih1, b_hh1);
    node_feat_kernel<<<(NN + 7) / 8, 256>>>(x, lin_w, att_src, att_dst);
    logit_max_kernel<<<(ETOT + 255) / 256, 256>>>(ei, ea);
    softmax_kernel<<<(ETOT + 255) / 256, 256>>>(ei, ea);
    alpha_kernel<<<(ETOT + 255) / 256, 256>>>(ei);
    message_kernel<<<(int)(((long long)ETOT * 32 + 255) / 256), 256>>>(ei);
    out_kernel<<<(NN * 32 + 255) / 256, 256>>>(gat_bias, fc_w, fc_b, out);
}